// round 16
// baseline (speedup 1.0000x reference)
#include <cuda_runtime.h>
#include <cfloat>
#include <cstdint>

#define NSETS 8
#define NPTS  4096
#define DF    16
#define KK    16
#define TPB   128          // 4 warps
#define QB    64           // queries per CTA (16 per warp)
#define CB    128          // candidates per tile
#define NT    (NPTS / CB)  // 32 tiles
#define DSTR  132          // D row stride (floats)
#define CSTR  132          // ct row stride (floats); 132%32=4 -> conflict-free B-frag LDS
#define QSTR  17

// dynamic smem layout (floats)
#define OFF_D   0                       // 64 * 132 = 8448   (aliased with qt during init)
#define OFF_CTH 8448                    // 16 * 132 = 2112
#define OFF_CTL 10560                   // 16 * 132 = 2112
#define OFF_CN  12672                   // 128
#define OFF_QN  12800                   // 64
#define SMEM_FLOATS 12864               // 51456 bytes

__device__ __forceinline__ uint32_t to_tf32(float f) {
    uint32_t u;
    asm("cvt.rna.tf32.f32 %0, %1;" : "=r"(u) : "f"(f));
    return u;
}

#define MMA_TF32(d0,d1,d2,d3,a0,a1,a2,a3,b0,b1)                                   \
    asm volatile("mma.sync.aligned.m16n8k8.row.col.f32.tf32.tf32.f32 "            \
                 "{%0,%1,%2,%3}, {%4,%5,%6,%7}, {%8,%9}, {%0,%1,%2,%3};"          \
                 : "+f"(d0), "+f"(d1), "+f"(d2), "+f"(d3)                         \
                 : "r"(a0), "r"(a1), "r"(a2), "r"(a3), "r"(b0), "r"(b1))

// paired drain in s-space (verified in R10-R14): lanes 0..15 hold list for sLo's
// query, lanes 16..31 for sHi's. Lists sorted DESCENDING in s (= ascending dist).
__device__ __forceinline__ void drain_pair_s(float& ls, int& li,
                                             float sLo, float sHi,
                                             float& tLo, float& tHi,
                                             int idx0, bool loHalf, int lane) {
    const unsigned FULL = 0xFFFFFFFFu;
    unsigned ballA = __ballot_sync(FULL, sLo > tLo);
    unsigned ballB = __ballot_sync(FULL, sHi > tHi);
    if (!(ballA | ballB)) return;
    while (ballA | ballB) {
        const bool hasA = (ballA != 0), hasB = (ballB != 0);
        const int bA = hasA ? (__ffs(ballA) - 1) : 0;
        const int bB = hasB ? (__ffs(ballB) - 1) : 0;
        ballA &= ballA - 1;
        ballB &= ballB - 1;
        const float svA = __shfl_sync(FULL, sLo, bA);
        const float svB = __shfl_sync(FULL, sHi, bB);
        const float sv = loHalf ? svA : svB;
        const int   iv = idx0 + (loHalf ? bA : bB);
        const bool valid = loHalf ? hasA : hasB;
        const float pv = __shfl_up_sync(FULL, ls, 1);
        const int   pi = __shfl_up_sync(FULL, li, 1);
        const bool lt  = (ls < sv);                   // strict: ties keep earlier idx
        const bool plt = (lane != 0 && lane != KK) && (pv < sv);
        if (valid && lt) {
            ls = plt ? pv : sv;
            li = plt ? pi : iv;
        }
    }
    tLo = __shfl_sync(FULL, ls, KK - 1);
    tHi = __shfl_sync(FULL, ls, 31);
}

__global__ __launch_bounds__(TPB)
void knn_tc(const float* __restrict__ x, float* __restrict__ out,
            long long out_elems) {
    extern __shared__ float sm[];
    float* Dm    = sm + OFF_D;
    float* qt    = sm + OFF_D;     // alias: consumed before D is written
    float* ct_hi = sm + OFF_CTH;
    float* ct_lo = sm + OFF_CTL;
    float* cn    = sm + OFF_CN;
    float* qn    = sm + OFF_QN;

    const int tid  = threadIdx.x;
    const int lane = tid & 31;
    const int wid  = tid >> 5;
    const unsigned FULL = 0xFFFFFFFFu;

    const int q0  = blockIdx.x * QB;       // global query id of CTA's first query
    const int set = q0 / NPTS;
    const int qr0 = q0 - set * NPTS;       // set-local first query row
    const float* __restrict__ xs = x + (size_t)set * NPTS * DF;

    // ---- stage CTA's 64 query rows + norms into smem (one-time) ----
    if (tid < QB) {
        const float4* src = reinterpret_cast<const float4*>(xs + (size_t)(qr0 + tid) * DF);
        float4 c0 = src[0], c1 = src[1], c2 = src[2], c3 = src[3];
        float* dst = qt + tid * QSTR;
        dst[0]=c0.x; dst[1]=c0.y; dst[2]=c0.z; dst[3]=c0.w;
        dst[4]=c1.x; dst[5]=c1.y; dst[6]=c1.z; dst[7]=c1.w;
        dst[8]=c2.x; dst[9]=c2.y; dst[10]=c2.z; dst[11]=c2.w;
        dst[12]=c3.x; dst[13]=c3.y; dst[14]=c3.z; dst[15]=c3.w;
        qn[tid] = -0.5f * (c0.x*c0.x + c0.y*c0.y + c0.z*c0.z + c0.w*c0.w
                         + c1.x*c1.x + c1.y*c1.y + c1.z*c1.z + c1.w*c1.w
                         + c2.x*c2.x + c2.y*c2.y + c2.z*c2.z + c2.w*c2.w
                         + c3.x*c3.x + c3.y*c3.y + c3.z*c3.z + c3.w*c3.w);
    }
    __syncthreads();

    // ---- per-warp A fragments (16 queries x 16 feats), hi/lo tf32 split ----
    const int g  = lane >> 2;              // 0..7
    const int tt = lane & 3;               // 0..3
    uint32_t ah[2][4], al[2][4];
#pragma unroll
    for (int ks = 0; ks < 2; ++ks) {
        const int r0 = 16 * wid + g;
        float v0 = qt[r0 * QSTR + 8 * ks + tt];
        float v1 = qt[(r0 + 8) * QSTR + 8 * ks + tt];
        float v2 = qt[r0 * QSTR + 8 * ks + tt + 4];
        float v3 = qt[(r0 + 8) * QSTR + 8 * ks + tt + 4];
        ah[ks][0] = to_tf32(v0);
        ah[ks][1] = to_tf32(v1);
        ah[ks][2] = to_tf32(v2);
        ah[ks][3] = to_tf32(v3);
        al[ks][0] = to_tf32(v0 - __uint_as_float(ah[ks][0]));
        al[ks][1] = to_tf32(v1 - __uint_as_float(ah[ks][1]));
        al[ks][2] = to_tf32(v2 - __uint_as_float(ah[ks][2]));
        al[ks][3] = to_tf32(v3 - __uint_as_float(ah[ks][3]));
    }
    const float qh0 = qn[16 * wid + g];
    const float qh1 = qn[16 * wid + g + 8];

    // distributed top-16 lists: layer L holds queries (2L, 2L+1) of this warp
    float ls[8];
    int   li[8];
    float thr[16];
#pragma unroll
    for (int L = 0; L < 8; ++L) { ls[L] = -FLT_MAX; li[L] = 0; }
#pragma unroll
    for (int q = 0; q < 16; ++q) thr[q] = -FLT_MAX;
    const bool loHalf = (lane < KK);

    for (int t = 0; t < NT; ++t) {
        // ---- stage candidate tile (128 rows) with tf32 hi/lo split ----
        {
            const float4* src = reinterpret_cast<const float4*>(
                xs + (size_t)(t * CB + tid) * DF);
            float4 c0 = src[0], c1 = src[1], c2 = src[2], c3 = src[3];
            float vv[16] = {c0.x,c0.y,c0.z,c0.w, c1.x,c1.y,c1.z,c1.w,
                            c2.x,c2.y,c2.z,c2.w, c3.x,c3.y,c3.z,c3.w};
            float nrm = 0.f;
#pragma unroll
            for (int k = 0; k < 16; ++k) nrm += vv[k] * vv[k];
            cn[tid] = -0.5f * nrm;
#pragma unroll
            for (int k = 0; k < 16; ++k) {
                uint32_t h = to_tf32(vv[k]);
                ct_hi[k * CSTR + tid] = __uint_as_float(h);
                ct_lo[k * CSTR + tid] = __uint_as_float(to_tf32(vv[k] - __uint_as_float(h)));
            }
        }
        __syncthreads();

        // ---- MMA phase: 16 queries x 128 candidates per warp ----
        for (int n = 0; n < 16; ++n) {
            const float cnh0 = cn[8 * n + 2 * tt];
            const float cnh1 = cn[8 * n + 2 * tt + 1];
            float d0 = qh0 + cnh0, d1 = qh0 + cnh1;
            float d2 = qh1 + cnh0, d3 = qh1 + cnh1;
#pragma unroll
            for (int ks = 0; ks < 2; ++ks) {
                uint32_t bh0 = __float_as_uint(ct_hi[(8 * ks + tt) * CSTR + 8 * n + g]);
                uint32_t bh1 = __float_as_uint(ct_hi[(8 * ks + tt + 4) * CSTR + 8 * n + g]);
                uint32_t bl0 = __float_as_uint(ct_lo[(8 * ks + tt) * CSTR + 8 * n + g]);
                uint32_t bl1 = __float_as_uint(ct_lo[(8 * ks + tt + 4) * CSTR + 8 * n + g]);
                MMA_TF32(d0,d1,d2,d3, ah[ks][0],ah[ks][1],ah[ks][2],ah[ks][3], bh0,bh1);
                MMA_TF32(d0,d1,d2,d3, ah[ks][0],ah[ks][1],ah[ks][2],ah[ks][3], bl0,bl1);
                MMA_TF32(d0,d1,d2,d3, al[ks][0],al[ks][1],al[ks][2],al[ks][3], bh0,bh1);
            }
            const int qr = 16 * wid + g;
            *reinterpret_cast<float2*>(&Dm[qr * DSTR + 8 * n + 2 * tt])       = make_float2(d0, d1);
            *reinterpret_cast<float2*>(&Dm[(qr + 8) * DSTR + 8 * n + 2 * tt]) = make_float2(d2, d3);
        }
        __syncthreads();

        // ---- selection: drain the 128 fresh s-values into 16 lists ----
        for (int s = 0; s < 4; ++s) {
            const int idx0 = t * CB + s * 32;
#pragma unroll
            for (int L = 0; L < 8; ++L) {
                const float sLo = Dm[(16 * wid + 2 * L) * DSTR + s * 32 + lane];
                const float sHi = Dm[(16 * wid + 2 * L + 1) * DSTR + s * 32 + lane];
                const bool hit = (sLo > thr[2 * L]) | (sHi > thr[2 * L + 1]);
                if (__ballot_sync(FULL, hit)) {
                    drain_pair_s(ls[L], li[L], sLo, sHi,
                                 thr[2 * L], thr[2 * L + 1], idx0, loHalf, lane);
                }
            }
        }
        // no extra barrier needed: next staging writes ct/cn (not D), and every
        // warp's MMA reads of ct finished before the post-MMA barrier above.
    }

    // ---- epilogue: dist = -2*s ----
    const long long E = (long long)NSETS * NPTS * KK;
    const int p = loHalf ? lane : (lane - KK);
#pragma unroll
    for (int L = 0; L < 8; ++L) {
        const int qg = q0 + 16 * wid + 2 * L + (loHalf ? 0 : 1);
        const float dv = -2.0f * ls[L];
        const long long b = (long long)qg * KK + p;
        if (out_elems >= 3 * E) {
            out[b]         = (float)qg;
            out[E + b]     = (float)(set * NPTS + li[L]);
            out[2 * E + b] = dv;
        } else {
            out[b] = dv;
        }
    }
}

extern "C" void kernel_launch(void* const* d_in, const int* in_sizes, int n_in,
                              void* d_out, int out_size) {
    const float* x = (const float*)d_in[0];
    float* out = (float*)d_out;
    const int smem_bytes = SMEM_FLOATS * sizeof(float);
    cudaFuncSetAttribute(knn_tc, cudaFuncAttributeMaxDynamicSharedMemorySize, smem_bytes);
    knn_tc<<<(NSETS * NPTS) / QB, TPB, smem_bytes>>>(x, out, (long long)out_size);
}